// round 8
// baseline (speedup 1.0000x reference)
#include <cuda_runtime.h>
#include <cuda_fp16.h>
#include <cstdint>

#define NN 100000
#define NE 3200000
#define HID 64
#define SCAN_B 512
#define NBLK1 ((NN + SCAN_B - 1) / SCAN_B)   // 196
#define TILE2 128
#define NT2 ((NN + TILE2 - 1) / TILE2)       // 782
#define HS_STRIDE 66                          // halves; conflict-free staging
#define ST_AGG  (1 << 28)
#define ST_PRE  (2 << 28)
#define VMASK   0x0FFFFFFF

// ---------------- scratch (device globals; no allocation) ----------------
__device__ int     g_cnt[NN];
__device__ float   g_dinv[NN];
__device__ float2  g_q[NN];            // q = dinv * x (layer-1 gather table)
__device__ int     g_row[NN + 1];      // CSR row pointers (by dst)
__device__ int     g_slot[NE];         // within-bucket slot per edge
__device__ int     g_sorted[NE];       // src ids sorted by dst
__device__ uint2   g_T[NN];            // (half2(xax,xay), half2(dinv,0)) per node
__device__ float   g_pool[HID];
__device__ int     g_part[NBLK1];      // lookback: status<<28 | value
__device__ int     g_done;
__device__ int     g_flag;             // 1 = edge_index stored as int64

// ---------------- kernels ----------------

// zero counters/pool/lookback state; thread 0 detects int64 vs int32.
__global__ void k_init(const unsigned long long* __restrict__ e64) {
    int i = blockIdx.x * blockDim.x + threadIdx.x;
    if (i < NN) g_cnt[i] = 0;
    if (i < HID) g_pool[i] = 0.0f;
    if (i < NBLK1) g_part[i] = 0;
    if (i == 0) {
        g_done = 0;
        int is64 = 1;
        #pragma unroll
        for (int k = 0; k < 8; k++)
            if (e64[k] >= (unsigned long long)NN) { is64 = 0; break; }
        g_flag = is64;
    }
}

// Histogram dst AND record each edge's slot within its bucket. 4 edges/thread.
__global__ void k_count(const void* __restrict__ edges) {
    int e0 = (blockIdx.x * blockDim.x + threadIdx.x) * 4;
    if (e0 >= NE) return;
    int d[4];
    if (g_flag) {
        const longlong2* d2 = (const longlong2*)((const long long*)edges + NE);
        longlong2 a = d2[e0 >> 1], b = d2[(e0 >> 1) + 1];
        d[0] = (int)a.x; d[1] = (int)a.y; d[2] = (int)b.x; d[3] = (int)b.y;
    } else {
        const int4* d4 = (const int4*)((const int*)edges + NE);
        int4 a = d4[e0 >> 2];
        d[0] = a.x; d[1] = a.y; d[2] = a.z; d[3] = a.w;
    }
    int sl[4];
    #pragma unroll
    for (int j = 0; j < 4; j++) sl[j] = atomicAdd(&g_cnt[d[j]], 1);
    *(int4*)&g_slot[e0] = make_int4(sl[0], sl[1], sl[2], sl[3]);
}

// Single-kernel exclusive scan (decoupled lookback) + dinv + q tables.
__global__ void __launch_bounds__(SCAN_B) k_scan(const float2* __restrict__ x2) {
    __shared__ int wsum[SCAN_B / 32];
    __shared__ int sh_total, sh_base;
    int bid = blockIdx.x, t = threadIdx.x;
    int i = bid * SCAN_B + t;
    int lane = t & 31, w = t >> 5;

    int v = (i < NN) ? g_cnt[i] : 0;
    int s = v;
    #pragma unroll
    for (int o = 1; o < 32; o <<= 1) {
        int u = __shfl_up_sync(0xffffffffu, s, o);
        if (lane >= o) s += u;
    }
    if (lane == 31) wsum[w] = s;
    __syncthreads();
    if (w == 0) {
        int ws = (lane < SCAN_B / 32) ? wsum[lane] : 0;
        #pragma unroll
        for (int o = 1; o < 16; o <<= 1) {
            int u = __shfl_up_sync(0xffffffffu, ws, o);
            if (lane >= o) ws += u;
        }
        if (lane < SCAN_B / 32) wsum[lane] = ws;
    }
    __syncthreads();
    int base_l = (w > 0) ? wsum[w - 1] : 0;
    int incl = s + base_l;                 // inclusive within block
    if (t == SCAN_B - 1) sh_total = incl;
    __syncthreads();
    int total = sh_total;

    // publish aggregate (or final prefix for block 0)
    if (t == 0) {
        int pk = (bid == 0) ? (ST_PRE | total) : (ST_AGG | total);
        *(volatile int*)&g_part[bid] = pk;
        __threadfence();
    }

    // warp 0: lookback for exclusive base
    if (bid == 0) {
        if (t == 0) sh_base = 0;
    } else if (w == 0) {
        int run = 0, lag = 1;
        for (;;) {
            int idx = bid - lag - lane;
            int pv = (idx >= 0) ? *(volatile int*)&g_part[idx] : ST_PRE;
            if (!__all_sync(0xffffffffu, (pv & ~VMASK) != 0)) continue;
            unsigned pm = __ballot_sync(0xffffffffu, (pv & ~VMASK) == ST_PRE);
            int val = pv & VMASK;
            if (pm) {
                int pl = __ffs(pm) - 1;
                int c = (lane <= pl) ? val : 0;
                #pragma unroll
                for (int o = 16; o > 0; o >>= 1) c += __shfl_xor_sync(0xffffffffu, c, o);
                run += c;
                break;
            } else {
                int c = val;
                #pragma unroll
                for (int o = 16; o > 0; o >>= 1) c += __shfl_xor_sync(0xffffffffu, c, o);
                run += c;
                lag += 32;
            }
        }
        if (lane == 0) {
            *(volatile int*)&g_part[bid] = ST_PRE | ((run + total) & VMASK);
            __threadfence();
            sh_base = run;
        }
    }
    __syncthreads();
    int base_g = sh_base;

    if (i < NN) {
        g_row[i] = base_g + incl - v;      // exclusive global prefix
        float d = rsqrtf((float)v + 1.0f);
        g_dinv[i] = d;
        float2 xv = x2[i];
        g_q[i] = make_float2(xv.x * d, xv.y * d);
    }
    if (bid == 0 && t == 0) g_row[NN] = NE;
}

// Atomic-free counting-sort scatter: addr = row[dst] + slot[e]. 4 edges/thread.
__global__ void k_scatter(const void* __restrict__ edges) {
    int e0 = (blockIdx.x * blockDim.x + threadIdx.x) * 4;
    if (e0 >= NE) return;
    int s[4], d[4];
    if (g_flag) {
        const longlong2* sp = (const longlong2*)edges;
        const longlong2* dp = (const longlong2*)((const long long*)edges + NE);
        longlong2 sa = sp[e0 >> 1], sb = sp[(e0 >> 1) + 1];
        longlong2 da = dp[e0 >> 1], db = dp[(e0 >> 1) + 1];
        s[0] = (int)sa.x; s[1] = (int)sa.y; s[2] = (int)sb.x; s[3] = (int)sb.y;
        d[0] = (int)da.x; d[1] = (int)da.y; d[2] = (int)db.x; d[3] = (int)db.y;
    } else {
        const int4* sp = (const int4*)edges;
        const int4* dp = (const int4*)((const int*)edges + NE);
        int4 sa = sp[e0 >> 2], da = dp[e0 >> 2];
        s[0] = sa.x; s[1] = sa.y; s[2] = sa.z; s[3] = sa.w;
        d[0] = da.x; d[1] = da.y; d[2] = da.z; d[3] = da.w;
    }
    int4 sl = *(const int4*)&g_slot[e0];
    g_sorted[__ldg(&g_row[d[0]]) + sl.x] = s[0];
    g_sorted[__ldg(&g_row[d[1]]) + sl.y] = s[1];
    g_sorted[__ldg(&g_row[d[2]]) + sl.z] = s[2];
    g_sorted[__ldg(&g_row[d[3]]) + sl.w] = s[3];
}

// Warp-per-node: layer-1 CSR gather of q -> T[n] = (xax, xay, dinv) fp16.
__global__ void __launch_bounds__(256) k_xa() {
    int gt = blockIdx.x * blockDim.x + threadIdx.x;
    int n = gt >> 5;
    if (n >= NN) return;
    int lane = gt & 31;

    int e0 = g_row[n], e1 = g_row[n + 1];
    float ax = 0.f, ay = 0.f;
    for (int e = e0 + lane; e < e1; e += 32) {
        float2 q = __ldg(&g_q[g_sorted[e]]);
        ax += q.x; ay += q.y;
    }
    #pragma unroll
    for (int o = 16; o > 0; o >>= 1) {
        ax += __shfl_xor_sync(0xffffffffu, ax, o);
        ay += __shfl_xor_sync(0xffffffffu, ay, o);
    }
    if (lane == 0) {
        float2 qn = g_q[n];
        float dv = g_dinv[n];
        __half2 a = __floats2half2_rn((ax + qn.x) * dv, (ay + qn.y) * dv);
        __half2 b = __floats2half2_rn(dv, 0.f);
        uint2 tv;
        tv.x = *(unsigned*)&a;
        tv.y = *(unsigned*)&b;
        g_T[n] = tv;
    }
}

// Fused: layer-2 agg via rank-2 reconstruction + node-batched h2 GEMV +
// relu + mean-pool + (last block) final FC output.
// 256 threads: fg = tid&7 (8 feats), rg = tid>>3; thread handles nodes rg*4+i.
__global__ void __launch_bounds__(256) k_gather2(
        const float* __restrict__ W1, const float* __restrict__ b1,
        const float* __restrict__ W2, const float* __restrict__ b2,
        const float* __restrict__ Wfc, const float* __restrict__ bfc,
        float* __restrict__ out) {
    __shared__ float  W2s[HID * HID];             // 16 KB, [k*64 + f]
    __shared__ __half hs[TILE2 * HS_STRIDE];      // 16.9 KB
    __shared__ int    sh_last;

    int tid = threadIdx.x;
    int fg = tid & 7, rg = tid >> 3;

    for (int i = tid; i < HID * HID; i += 256) W2s[i] = W2[i];
    float bloc[8];
    #pragma unroll
    for (int j = 0; j < 8; j++) bloc[j] = __ldg(&b2[8 * fg + j]);
    // layer-1 weights for this thread's 8 features, as half2 pairs
    __half2 w0[4], w1[4], bb1[4];
    {
        int f0 = 8 * fg;
        #pragma unroll
        for (int j = 0; j < 4; j++) {
            w0[j]  = __floats2half2_rn(__ldg(&W1[f0 + 2 * j]),       __ldg(&W1[f0 + 2 * j + 1]));
            w1[j]  = __floats2half2_rn(__ldg(&W1[HID + f0 + 2 * j]), __ldg(&W1[HID + f0 + 2 * j + 1]));
            bb1[j] = __floats2half2_rn(__ldg(&b1[f0 + 2 * j]),       __ldg(&b1[f0 + 2 * j + 1]));
        }
    }
    __syncthreads();

    float pool8[8] = {0.f, 0.f, 0.f, 0.f, 0.f, 0.f, 0.f, 0.f};
    const __half2 hz = __floats2half2_rn(0.f, 0.f);

    for (int tile = blockIdx.x; tile < NT2; tile += gridDim.x) {
        // ---- stage A: reconstruct-and-accumulate agg for 4 nodes ----
        #pragma unroll
        for (int i = 0; i < 4; i++) {
            int nl = rg * 4 + i;
            int n = tile * TILE2 + nl;
            float acc[8] = {0.f, 0.f, 0.f, 0.f, 0.f, 0.f, 0.f, 0.f};
            if (n < NN) {
                int e0 = g_row[n], e1 = g_row[n + 1];
                __half2 pa[4];
                #pragma unroll
                for (int j = 0; j < 4; j++) pa[j] = hz;
                int e = e0;
                for (; e + 4 <= e1; e += 4) {
                    int  sI[4];
                    uint2 tv[4];
                    #pragma unroll
                    for (int u = 0; u < 4; u++) sI[u] = __ldg(&g_sorted[e + u]);
                    #pragma unroll
                    for (int u = 0; u < 4; u++) tv[u] = __ldg(&g_T[sI[u]]);
                    #pragma unroll
                    for (int u = 0; u < 4; u++) {
                        __half2 xa2 = *(__half2*)&tv[u].x;
                        __half2 dvp = *(__half2*)&tv[u].y;
                        __half2 axs = __low2half2(xa2);
                        __half2 ays = __high2half2(xa2);
                        __half2 dvs = __low2half2(dvp);
                        #pragma unroll
                        for (int j = 0; j < 4; j++) {
                            __half2 r = __hfma2(axs, w0[j], __hfma2(ays, w1[j], bb1[j]));
                            r = __hmax2(r, hz);
                            pa[j] = __hfma2(r, dvs, pa[j]);
                        }
                    }
                }
                for (; e < e1; e++) {
                    uint2 tv = __ldg(&g_T[__ldg(&g_sorted[e])]);
                    __half2 xa2 = *(__half2*)&tv.x;
                    __half2 dvp = *(__half2*)&tv.y;
                    __half2 axs = __low2half2(xa2);
                    __half2 ays = __high2half2(xa2);
                    __half2 dvs = __low2half2(dvp);
                    #pragma unroll
                    for (int j = 0; j < 4; j++) {
                        __half2 r = __hfma2(axs, w0[j], __hfma2(ays, w1[j], bb1[j]));
                        r = __hmax2(r, hz);
                        pa[j] = __hfma2(r, dvs, pa[j]);
                    }
                }
                // self loop (same reconstruction, s = n)
                {
                    uint2 tv = g_T[n];
                    __half2 xa2 = *(__half2*)&tv.x;
                    __half2 dvp = *(__half2*)&tv.y;
                    __half2 axs = __low2half2(xa2);
                    __half2 ays = __high2half2(xa2);
                    __half2 dvs = __low2half2(dvp);
                    #pragma unroll
                    for (int j = 0; j < 4; j++) {
                        __half2 r = __hfma2(axs, w0[j], __hfma2(ays, w1[j], bb1[j]));
                        r = __hmax2(r, hz);
                        pa[j] = __hfma2(r, dvs, pa[j]);
                    }
                }
                float sc = g_dinv[n];
                #pragma unroll
                for (int j = 0; j < 4; j++) {
                    float2 f2 = __half22float2(pa[j]);
                    acc[2 * j]     = f2.x * sc;
                    acc[2 * j + 1] = f2.y * sc;
                }
            }
            __half2* hw = (__half2*)&hs[nl * HS_STRIDE + 8 * fg];
            #pragma unroll
            for (int j = 0; j < 4; j++)
                hw[j] = __floats2half2_rn(acc[2 * j], acc[2 * j + 1]);
        }
        __syncthreads();

        // ---- stage B: h2 GEMV for 4 nodes, W2 smem reads amortized 4x ----
        float o[4][8];
        #pragma unroll
        for (int i = 0; i < 4; i++)
            #pragma unroll
            for (int j = 0; j < 8; j++) o[i][j] = bloc[j];

        const __half* hp0 = &hs[(rg * 4 + 0) * HS_STRIDE];
        const __half* hp1 = &hs[(rg * 4 + 1) * HS_STRIDE];
        const __half* hp2 = &hs[(rg * 4 + 2) * HS_STRIDE];
        const __half* hp3 = &hs[(rg * 4 + 3) * HS_STRIDE];
        #pragma unroll 4
        for (int k = 0; k < HID; k++) {
            float a0 = __half2float(hp0[k]);
            float a1 = __half2float(hp1[k]);
            float a2 = __half2float(hp2[k]);
            float a3 = __half2float(hp3[k]);
            float4 wA = *(const float4*)&W2s[k * HID + 8 * fg];
            float4 wB = *(const float4*)&W2s[k * HID + 8 * fg + 4];
            o[0][0] = fmaf(a0, wA.x, o[0][0]); o[0][1] = fmaf(a0, wA.y, o[0][1]);
            o[0][2] = fmaf(a0, wA.z, o[0][2]); o[0][3] = fmaf(a0, wA.w, o[0][3]);
            o[0][4] = fmaf(a0, wB.x, o[0][4]); o[0][5] = fmaf(a0, wB.y, o[0][5]);
            o[0][6] = fmaf(a0, wB.z, o[0][6]); o[0][7] = fmaf(a0, wB.w, o[0][7]);
            o[1][0] = fmaf(a1, wA.x, o[1][0]); o[1][1] = fmaf(a1, wA.y, o[1][1]);
            o[1][2] = fmaf(a1, wA.z, o[1][2]); o[1][3] = fmaf(a1, wA.w, o[1][3]);
            o[1][4] = fmaf(a1, wB.x, o[1][4]); o[1][5] = fmaf(a1, wB.y, o[1][5]);
            o[1][6] = fmaf(a1, wB.z, o[1][6]); o[1][7] = fmaf(a1, wB.w, o[1][7]);
            o[2][0] = fmaf(a2, wA.x, o[2][0]); o[2][1] = fmaf(a2, wA.y, o[2][1]);
            o[2][2] = fmaf(a2, wA.z, o[2][2]); o[2][3] = fmaf(a2, wA.w, o[2][3]);
            o[2][4] = fmaf(a2, wB.x, o[2][4]); o[2][5] = fmaf(a2, wB.y, o[2][5]);
            o[2][6] = fmaf(a2, wB.z, o[2][6]); o[2][7] = fmaf(a2, wB.w, o[2][7]);
            o[3][0] = fmaf(a3, wA.x, o[3][0]); o[3][1] = fmaf(a3, wA.y, o[3][1]);
            o[3][2] = fmaf(a3, wA.z, o[3][2]); o[3][3] = fmaf(a3, wA.w, o[3][3]);
            o[3][4] = fmaf(a3, wB.x, o[3][4]); o[3][5] = fmaf(a3, wB.y, o[3][5]);
            o[3][6] = fmaf(a3, wB.z, o[3][6]); o[3][7] = fmaf(a3, wB.w, o[3][7]);
        }
        #pragma unroll
        for (int i = 0; i < 4; i++) {
            int n = tile * TILE2 + rg * 4 + i;
            if (n < NN) {
                #pragma unroll
                for (int j = 0; j < 8; j++)
                    pool8[j] += fmaxf(o[i][j], 0.f);
            }
        }
        __syncthreads();   // hs reused next tile
    }

    // ---- pool reduction (reuse hs as float scratch) ----
    float* hsf = (float*)hs;   // 32*64 floats = 8 KB
    #pragma unroll
    for (int j = 0; j < 8; j++)
        hsf[rg * HID + 8 * fg + j] = pool8[j];
    __syncthreads();
    if (tid < HID) {
        float s = 0.f;
        #pragma unroll 8
        for (int r = 0; r < 32; r++) s += hsf[r * HID + tid];
        atomicAdd(&g_pool[tid], s);
    }

    // ---- last block computes the final FC output ----
    if (tid == 0) {
        __threadfence();
        int t = atomicAdd(&g_done, 1);
        sh_last = (t == gridDim.x - 1);
    }
    __syncthreads();
    if (sh_last && tid < 32) {
        float s = g_pool[tid] * __ldg(&Wfc[tid]) + g_pool[tid + 32] * __ldg(&Wfc[tid + 32]);
        #pragma unroll
        for (int o2 = 16; o2 > 0; o2 >>= 1) s += __shfl_down_sync(0xffffffffu, s, o2);
        if (tid == 0) out[0] = s * (1.0f / NN) + __ldg(&bfc[0]);
    }
}

// ---------------- launch ----------------
extern "C" void kernel_launch(void* const* d_in, const int* in_sizes, int n_in,
                              void* d_out, int out_size) {
    const float2* x2    = (const float2*)d_in[0];
    const void*   edges = d_in[1];
    const float*  W1    = (const float*)d_in[2];
    const float*  b1    = (const float*)d_in[3];
    const float*  W2    = (const float*)d_in[4];
    const float*  b2    = (const float*)d_in[5];
    const float*  Wfc   = (const float*)d_in[6];
    const float*  bfc   = (const float*)d_in[7];
    float* out = (float*)d_out;

    const int T = 256;
    k_init<<<(NN + T - 1) / T, T>>>((const unsigned long long*)edges);
    k_count<<<(NE / 4 + T - 1) / T, T>>>(edges);
    k_scan<<<NBLK1, SCAN_B>>>(x2);
    k_scatter<<<(NE / 4 + T - 1) / T, T>>>(edges);
    k_xa<<<(NN * 32 + T - 1) / T, T>>>();
    k_gather2<<<NT2, T>>>(W1, b1, W2, b2, Wfc, bfc, out);
}

// round 9
// speedup vs baseline: 1.1423x; 1.1423x over previous
#include <cuda_runtime.h>
#include <cuda_fp16.h>
#include <cstdint>

#define NN 100000
#define NE 3200000
#define HID 64
#define SCAN_B 512
#define NBLK1 ((NN + SCAN_B - 1) / SCAN_B)   // 196
#define TILE2 128
#define NT2 ((NN + TILE2 - 1) / TILE2)       // 782
#define HS_STRIDE 66                          // halves; conflict-free staging
#define ST_AGG  (1 << 28)
#define ST_PRE  (2 << 28)
#define VMASK   0x0FFFFFFF

// ---------------- scratch (device globals; no allocation) ----------------
__device__ int     g_cnt[NN];
__device__ float   g_dinv[NN];
__device__ float2  g_q[NN];            // q = dinv * x (layer-1 gather table)
__device__ int     g_row[NN + 1];      // CSR row pointers (by dst)
__device__ int     g_slot[NE];         // within-bucket slot per edge
__device__ int     g_sorted[NE];       // src ids sorted by dst
__device__ __half2 g_ph[NN * 32];      // p = dinv*relu(h1), fp16, 128 B/node
__device__ float   g_pool[HID];
__device__ int     g_part[NBLK1];      // lookback: status<<28 | value
__device__ int     g_done;
__device__ int     g_flag;             // 1 = edge_index stored as int64

// ---------------- kernels ----------------

// zero counters/pool/lookback state; thread 0 detects int64 vs int32.
__global__ void k_init(const unsigned long long* __restrict__ e64) {
    int i = blockIdx.x * blockDim.x + threadIdx.x;
    if (i < NN) g_cnt[i] = 0;
    if (i < HID) g_pool[i] = 0.0f;
    if (i < NBLK1) g_part[i] = 0;
    if (i == 0) {
        g_done = 0;
        int is64 = 1;
        #pragma unroll
        for (int k = 0; k < 8; k++)
            if (e64[k] >= (unsigned long long)NN) { is64 = 0; break; }
        g_flag = is64;
    }
}

// Histogram dst AND record each edge's slot within its bucket. 4 edges/thread.
__global__ void k_count(const void* __restrict__ edges) {
    int e0 = (blockIdx.x * blockDim.x + threadIdx.x) * 4;
    if (e0 >= NE) return;
    int d[4];
    if (g_flag) {
        const longlong2* d2 = (const longlong2*)((const long long*)edges + NE);
        longlong2 a = d2[e0 >> 1], b = d2[(e0 >> 1) + 1];
        d[0] = (int)a.x; d[1] = (int)a.y; d[2] = (int)b.x; d[3] = (int)b.y;
    } else {
        const int4* d4 = (const int4*)((const int*)edges + NE);
        int4 a = d4[e0 >> 2];
        d[0] = a.x; d[1] = a.y; d[2] = a.z; d[3] = a.w;
    }
    int sl[4];
    #pragma unroll
    for (int j = 0; j < 4; j++) sl[j] = atomicAdd(&g_cnt[d[j]], 1);
    *(int4*)&g_slot[e0] = make_int4(sl[0], sl[1], sl[2], sl[3]);
}

// Single-kernel exclusive scan (decoupled lookback) + dinv + q tables.
__global__ void __launch_bounds__(SCAN_B) k_scan(const float2* __restrict__ x2) {
    __shared__ int wsum[SCAN_B / 32];
    __shared__ int sh_total, sh_base;
    int bid = blockIdx.x, t = threadIdx.x;
    int i = bid * SCAN_B + t;
    int lane = t & 31, w = t >> 5;

    int v = (i < NN) ? g_cnt[i] : 0;
    int s = v;
    #pragma unroll
    for (int o = 1; o < 32; o <<= 1) {
        int u = __shfl_up_sync(0xffffffffu, s, o);
        if (lane >= o) s += u;
    }
    if (lane == 31) wsum[w] = s;
    __syncthreads();
    if (w == 0) {
        int ws = (lane < SCAN_B / 32) ? wsum[lane] : 0;
        #pragma unroll
        for (int o = 1; o < 16; o <<= 1) {
            int u = __shfl_up_sync(0xffffffffu, ws, o);
            if (lane >= o) ws += u;
        }
        if (lane < SCAN_B / 32) wsum[lane] = ws;
    }
    __syncthreads();
    int base_l = (w > 0) ? wsum[w - 1] : 0;
    int incl = s + base_l;                 // inclusive within block
    if (t == SCAN_B - 1) sh_total = incl;
    __syncthreads();
    int total = sh_total;

    if (t == 0) {
        int pk = (bid == 0) ? (ST_PRE | total) : (ST_AGG | total);
        *(volatile int*)&g_part[bid] = pk;
        __threadfence();
    }

    if (bid == 0) {
        if (t == 0) sh_base = 0;
    } else if (w == 0) {
        int run = 0, lag = 1;
        for (;;) {
            int idx = bid - lag - lane;
            int pv = (idx >= 0) ? *(volatile int*)&g_part[idx] : ST_PRE;
            if (!__all_sync(0xffffffffu, (pv & ~VMASK) != 0)) continue;
            unsigned pm = __ballot_sync(0xffffffffu, (pv & ~VMASK) == ST_PRE);
            int val = pv & VMASK;
            if (pm) {
                int pl = __ffs(pm) - 1;
                int c = (lane <= pl) ? val : 0;
                #pragma unroll
                for (int o = 16; o > 0; o >>= 1) c += __shfl_xor_sync(0xffffffffu, c, o);
                run += c;
                break;
            } else {
                int c = val;
                #pragma unroll
                for (int o = 16; o > 0; o >>= 1) c += __shfl_xor_sync(0xffffffffu, c, o);
                run += c;
                lag += 32;
            }
        }
        if (lane == 0) {
            *(volatile int*)&g_part[bid] = ST_PRE | ((run + total) & VMASK);
            __threadfence();
            sh_base = run;
        }
    }
    __syncthreads();
    int base_g = sh_base;

    if (i < NN) {
        g_row[i] = base_g + incl - v;      // exclusive global prefix
        float d = rsqrtf((float)v + 1.0f);
        g_dinv[i] = d;
        float2 xv = x2[i];
        g_q[i] = make_float2(xv.x * d, xv.y * d);
    }
    if (bid == 0 && t == 0) g_row[NN] = NE;
}

// Atomic-free counting-sort scatter: addr = row[dst] + slot[e]. 8 edges/thread.
__global__ void k_scatter(const void* __restrict__ edges) {
    int e0 = (blockIdx.x * blockDim.x + threadIdx.x) * 8;
    if (e0 >= NE) return;
    int s[8], d[8];
    if (g_flag) {
        const longlong2* sp = (const longlong2*)edges;
        const longlong2* dp = (const longlong2*)((const long long*)edges + NE);
        #pragma unroll
        for (int j = 0; j < 4; j++) {
            longlong2 sv = sp[(e0 >> 1) + j], dv = dp[(e0 >> 1) + j];
            s[2 * j] = (int)sv.x; s[2 * j + 1] = (int)sv.y;
            d[2 * j] = (int)dv.x; d[2 * j + 1] = (int)dv.y;
        }
    } else {
        const int4* sp = (const int4*)edges;
        const int4* dp = (const int4*)((const int*)edges + NE);
        #pragma unroll
        for (int j = 0; j < 2; j++) {
            int4 sv = sp[(e0 >> 2) + j], dv = dp[(e0 >> 2) + j];
            s[4 * j] = sv.x; s[4 * j + 1] = sv.y; s[4 * j + 2] = sv.z; s[4 * j + 3] = sv.w;
            d[4 * j] = dv.x; d[4 * j + 1] = dv.y; d[4 * j + 2] = dv.z; d[4 * j + 3] = dv.w;
        }
    }
    int4 sa = *(const int4*)&g_slot[e0];
    int4 sb = *(const int4*)&g_slot[e0 + 4];
    int sl[8] = {sa.x, sa.y, sa.z, sa.w, sb.x, sb.y, sb.z, sb.w};
    int r[8];
    #pragma unroll
    for (int j = 0; j < 8; j++) r[j] = __ldg(&g_row[d[j]]);
    #pragma unroll
    for (int j = 0; j < 8; j++) g_sorted[r[j] + sl[j]] = s[j];
}

// Warp-per-node: layer-1 CSR gather of q + 2->64 GEMV + relu -> fp16 p row.
__global__ void __launch_bounds__(256) k_h1p(const float* __restrict__ W1,
                                             const float* __restrict__ b1) {
    int gt = blockIdx.x * blockDim.x + threadIdx.x;
    int n = gt >> 5;
    if (n >= NN) return;
    int lane = gt & 31;

    int e0 = g_row[n], e1 = g_row[n + 1];
    float ax = 0.f, ay = 0.f;
    for (int e = e0 + lane; e < e1; e += 32) {
        float2 q = __ldg(&g_q[g_sorted[e]]);
        ax += q.x; ay += q.y;
    }
    #pragma unroll
    for (int o = 16; o > 0; o >>= 1) {
        ax += __shfl_xor_sync(0xffffffffu, ax, o);
        ay += __shfl_xor_sync(0xffffffffu, ay, o);
    }
    float2 qn = g_q[n];
    float dv = g_dinv[n];
    float xax = (ax + qn.x) * dv;
    float xay = (ay + qn.y) * dv;

    int f = 2 * lane;
    float v0 = fmaf(xax, __ldg(&W1[f]),     fmaf(xay, __ldg(&W1[HID + f]),     __ldg(&b1[f])));
    float v1 = fmaf(xax, __ldg(&W1[f + 1]), fmaf(xay, __ldg(&W1[HID + f + 1]), __ldg(&b1[f + 1])));
    v0 = fmaxf(v0, 0.0f) * dv;
    v1 = fmaxf(v1, 0.0f) * dv;
    g_ph[n * 32 + lane] = __floats2half2_rn(v0, v1);
}

// Fused: fp16 CSR gather (layer-2 agg) + node-batched h2 GEMV + relu + pool
// + (last block) final FC output.
// 256 threads: fg = tid&7 (8 feats), rg = tid>>3; thread handles nodes rg*4+i.
__global__ void __launch_bounds__(256) k_gather2(
        const float* __restrict__ W2, const float* __restrict__ b2,
        const float* __restrict__ Wfc, const float* __restrict__ bfc,
        float* __restrict__ out) {
    __shared__ float  W2s[HID * HID];             // 16 KB, [k*64 + f]
    __shared__ __half hs[TILE2 * HS_STRIDE];      // 16.9 KB
    __shared__ int    sh_last;

    int tid = threadIdx.x;
    int fg = tid & 7, rg = tid >> 3;

    for (int i = tid; i < HID * HID; i += 256) W2s[i] = W2[i];
    float bloc[8];
    #pragma unroll
    for (int j = 0; j < 8; j++) bloc[j] = __ldg(&b2[8 * fg + j]);
    __syncthreads();

    float pool8[8] = {0.f, 0.f, 0.f, 0.f, 0.f, 0.f, 0.f, 0.f};
    const uint4* pt = (const uint4*)g_ph;

    for (int tile = blockIdx.x; tile < NT2; tile += gridDim.x) {
        // -------- stage A: gather agg for 4 nodes, write fp16 to hs --------
        #pragma unroll
        for (int i = 0; i < 4; i++) {
            int nl = rg * 4 + i;
            int n = tile * TILE2 + nl;
            float acc[8] = {0.f, 0.f, 0.f, 0.f, 0.f, 0.f, 0.f, 0.f};
            if (n < NN) {
                int e0 = g_row[n], e1 = g_row[n + 1];
                __half2 pa[4][4];
                #pragma unroll
                for (int j = 0; j < 4; j++)
                    #pragma unroll
                    for (int k = 0; k < 4; k++)
                        pa[j][k] = __floats2half2_rn(0.f, 0.f);
                int e = e0;
                for (; e + 4 <= e1; e += 4) {
                    #pragma unroll
                    for (int j = 0; j < 4; j++) {
                        int s = __ldg(&g_sorted[e + j]);
                        uint4 r = __ldg(&pt[s * 8 + fg]);
                        pa[j][0] = __hadd2(pa[j][0], *(__half2*)&r.x);
                        pa[j][1] = __hadd2(pa[j][1], *(__half2*)&r.y);
                        pa[j][2] = __hadd2(pa[j][2], *(__half2*)&r.z);
                        pa[j][3] = __hadd2(pa[j][3], *(__half2*)&r.w);
                    }
                }
                for (; e < e1; e++) {
                    int s = __ldg(&g_sorted[e]);
                    uint4 r = __ldg(&pt[s * 8 + fg]);
                    pa[0][0] = __hadd2(pa[0][0], *(__half2*)&r.x);
                    pa[0][1] = __hadd2(pa[0][1], *(__half2*)&r.y);
                    pa[0][2] = __hadd2(pa[0][2], *(__half2*)&r.z);
                    pa[0][3] = __hadd2(pa[0][3], *(__half2*)&r.w);
                }
                #pragma unroll
                for (int j = 0; j < 4; j++) {
                    #pragma unroll
                    for (int k = 0; k < 4; k++) {
                        float2 f2 = __half22float2(pa[j][k]);
                        acc[2 * k]     += f2.x;
                        acc[2 * k + 1] += f2.y;
                    }
                }
                // self loop in fp32
                uint4 rs = pt[n * 8 + fg];
                float2 s0 = __half22float2(*(__half2*)&rs.x);
                float2 s1 = __half22float2(*(__half2*)&rs.y);
                float2 s2 = __half22float2(*(__half2*)&rs.z);
                float2 s3 = __half22float2(*(__half2*)&rs.w);
                acc[0] += s0.x; acc[1] += s0.y; acc[2] += s1.x; acc[3] += s1.y;
                acc[4] += s2.x; acc[5] += s2.y; acc[6] += s3.x; acc[7] += s3.y;
                float sc = g_dinv[n];
                #pragma unroll
                for (int k = 0; k < 8; k++) acc[k] *= sc;
            }
            __half2* hw = (__half2*)&hs[nl * HS_STRIDE + 8 * fg];
            #pragma unroll
            for (int j = 0; j < 4; j++)
                hw[j] = __floats2half2_rn(acc[2 * j], acc[2 * j + 1]);
        }
        __syncthreads();

        // -------- stage B: h2 GEMV for 4 nodes, W2 amortized 4x --------
        float o[4][8];
        #pragma unroll
        for (int i = 0; i < 4; i++)
            #pragma unroll
            for (int j = 0; j < 8; j++) o[i][j] = bloc[j];

        const __half* hp0 = &hs[(rg * 4 + 0) * HS_STRIDE];
        const __half* hp1 = &hs[(rg * 4 + 1) * HS_STRIDE];
        const __half* hp2 = &hs[(rg * 4 + 2) * HS_STRIDE];
        const __half* hp3 = &hs[(rg * 4 + 3) * HS_STRIDE];
        #pragma unroll 4
        for (int k = 0; k < HID; k++) {
            float a0 = __half2float(hp0[k]);
            float a1 = __half2float(hp1[k]);
            float a2 = __half2float(hp2[k]);
            float a3 = __half2float(hp3[k]);
            float4 wA = *(const float4*)&W2s[k * HID + 8 * fg];
            float4 wB = *(const float4*)&W2s[k * HID + 8 * fg + 4];
            o[0][0] = fmaf(a0, wA.x, o[0][0]); o[0][1] = fmaf(a0, wA.y, o[0][1]);
            o[0][2] = fmaf(a0, wA.z, o[0][2]); o[0][3] = fmaf(a0, wA.w, o[0][3]);
            o[0][4] = fmaf(a0, wB.x, o[0][4]); o[0][5] = fmaf(a0, wB.y, o[0][5]);
            o[0][6] = fmaf(a0, wB.z, o[0][6]); o[0][7] = fmaf(a0, wB.w, o[0][7]);
            o[1][0] = fmaf(a1, wA.x, o[1][0]); o[1][1] = fmaf(a1, wA.y, o[1][1]);
            o[1][2] = fmaf(a1, wA.z, o[1][2]); o[1][3] = fmaf(a1, wA.w, o[1][3]);
            o[1][4] = fmaf(a1, wB.x, o[1][4]); o[1][5] = fmaf(a1, wB.y, o[1][5]);
            o[1][6] = fmaf(a1, wB.z, o[1][6]); o[1][7] = fmaf(a1, wB.w, o[1][7]);
            o[2][0] = fmaf(a2, wA.x, o[2][0]); o[2][1] = fmaf(a2, wA.y, o[2][1]);
            o[2][2] = fmaf(a2, wA.z, o[2][2]); o[2][3] = fmaf(a2, wA.w, o[2][3]);
            o[2][4] = fmaf(a2, wB.x, o[2][4]); o[2][5] = fmaf(a2, wB.y, o[2][5]);
            o[2][6] = fmaf(a2, wB.z, o[2][6]); o[2][7] = fmaf(a2, wB.w, o[2][7]);
            o[3][0] = fmaf(a3, wA.x, o[3][0]); o[3][1] = fmaf(a3, wA.y, o[3][1]);
            o[3][2] = fmaf(a3, wA.z, o[3][2]); o[3][3] = fmaf(a3, wA.w, o[3][3]);
            o[3][4] = fmaf(a3, wB.x, o[3][4]); o[3][5] = fmaf(a3, wB.y, o[3][5]);
            o[3][6] = fmaf(a3, wB.z, o[3][6]); o[3][7] = fmaf(a3, wB.w, o[3][7]);
        }
        #pragma unroll
        for (int i = 0; i < 4; i++) {
            int n = tile * TILE2 + rg * 4 + i;
            if (n < NN) {
                #pragma unroll
                for (int j = 0; j < 8; j++)
                    pool8[j] += fmaxf(o[i][j], 0.f);
            }
        }
        __syncthreads();   // hs reused next tile
    }

    // -------- final pool reduction (reuse hs as float scratch) --------
    float* hsf = (float*)hs;   // 32*64 floats = 8 KB
    #pragma unroll
    for (int j = 0; j < 8; j++)
        hsf[rg * HID + 8 * fg + j] = pool8[j];
    __syncthreads();
    if (tid < HID) {
        float s = 0.f;
        #pragma unroll 8
        for (int r = 0; r < 32; r++) s += hsf[r * HID + tid];
        atomicAdd(&g_pool[tid], s);
    }

    // -------- last block computes the final FC output --------
    if (tid == 0) {
        __threadfence();
        int t = atomicAdd(&g_done, 1);
        sh_last = (t == gridDim.x - 1);
    }
    __syncthreads();
    if (sh_last && tid < 32) {
        float s = g_pool[tid] * __ldg(&Wfc[tid]) + g_pool[tid + 32] * __ldg(&Wfc[tid + 32]);
        #pragma unroll
        for (int o2 = 16; o2 > 0; o2 >>= 1) s += __shfl_down_sync(0xffffffffu, s, o2);
        if (tid == 0) out[0] = s * (1.0f / NN) + __ldg(&bfc[0]);
    }
}

// ---------------- launch ----------------
extern "C" void kernel_launch(void* const* d_in, const int* in_sizes, int n_in,
                              void* d_out, int out_size) {
    const float2* x2    = (const float2*)d_in[0];
    const void*   edges = d_in[1];
    const float*  W1    = (const float*)d_in[2];
    const float*  b1    = (const float*)d_in[3];
    const float*  W2    = (const float*)d_in[4];
    const float*  b2    = (const float*)d_in[5];
    const float*  Wfc   = (const float*)d_in[6];
    const float*  bfc   = (const float*)d_in[7];
    float* out = (float*)d_out;

    const int T = 256;
    k_init<<<(NN + T - 1) / T, T>>>((const unsigned long long*)edges);
    k_count<<<(NE / 4 + T - 1) / T, T>>>(edges);
    k_scan<<<NBLK1, SCAN_B>>>(x2);
    k_scatter<<<(NE / 8 + T - 1) / T, T>>>(edges);
    k_h1p<<<(NN * 32 + T - 1) / T, T>>>(W1, b1);
    k_gather2<<<NT2, T>>>(W2, b2, Wfc, bfc, out);
}